// round 1
// baseline (speedup 1.0000x reference)
#include <cuda_runtime.h>
#include <math.h>

#define Bb 128
#define Tt 128
#define Vv 10000
#define Ee 256
#define Hh 1024
#define Dd 128
#define G3 3072           // 3*H
#define MROWS (Bb*Tt)     // 16384

// Scratch (static __device__ globals: allowed; zero-initialized at load)
__device__ float g_xg[MROWS * G3];     // [T][B][3H]  input-side gate pre-activations (incl. bi)
__device__ float g_hs[MROWS * Hh];     // [T][B][H]   hidden states per step
__device__ float g_d [MROWS * Dd];     // [T][B][D]   relu(hs@w1+b1)
__device__ float g_hzero[Bb * Hh];     // stays all-zero: h_{-1}

// ---------------------------------------------------------------------------
// Kernel 1: xg[t*B+b][:] = emb[tokens[b][t]] @ gru_k + gru_bi
// M=16384, N=3072, K=256.  64x64 tile, BK=16, 256 thr, 4x4 micro-tile.
// ---------------------------------------------------------------------------
__global__ __launch_bounds__(256) void k_embed_gemm(
    const int* __restrict__ tokens, const float* __restrict__ emb,
    const float* __restrict__ gk, const float* __restrict__ bi)
{
    __shared__ float As[16][68];   // [k][m]
    __shared__ float Bs[16][68];   // [k][n]
    const int n0 = blockIdx.x * 64;
    const int m0 = blockIdx.y * 64;
    const int tid = threadIdx.x;
    const int tx = tid & 15, ty = tid >> 4;
    const int a_row = tid >> 2, a_c4 = tid & 3;
    const int b_row = tid >> 4, b_c4 = tid & 15;
    const int r = m0 + a_row;                       // r = t*B + b
    const int tok = tokens[(r & 127) * Tt + (r >> 7)];   // tokens[b][t]
    const float4* __restrict__ apt =
        reinterpret_cast<const float4*>(emb + (size_t)tok * Ee);

    float acc[4][4];
#pragma unroll
    for (int i = 0; i < 4; i++)
#pragma unroll
        for (int j = 0; j < 4; j++) acc[i][j] = 0.f;

    for (int k0 = 0; k0 < Ee; k0 += 16) {
        float4 av = apt[(k0 >> 2) + a_c4];
        float4 bv = *reinterpret_cast<const float4*>(
            gk + (size_t)(k0 + b_row) * G3 + n0 + b_c4 * 4);
        As[a_c4 * 4 + 0][a_row] = av.x;
        As[a_c4 * 4 + 1][a_row] = av.y;
        As[a_c4 * 4 + 2][a_row] = av.z;
        As[a_c4 * 4 + 3][a_row] = av.w;
        *reinterpret_cast<float4*>(&Bs[b_row][b_c4 * 4]) = bv;
        __syncthreads();
#pragma unroll
        for (int kk = 0; kk < 16; kk++) {
            float4 a = *reinterpret_cast<const float4*>(&As[kk][ty * 4]);
            float4 b = *reinterpret_cast<const float4*>(&Bs[kk][tx * 4]);
            float aa[4] = {a.x, a.y, a.z, a.w};
            float bb[4] = {b.x, b.y, b.z, b.w};
#pragma unroll
            for (int i = 0; i < 4; i++)
#pragma unroll
                for (int j = 0; j < 4; j++)
                    acc[i][j] = fmaf(aa[i], bb[j], acc[i][j]);
        }
        __syncthreads();
    }
#pragma unroll
    for (int i = 0; i < 4; i++) {
        int row = m0 + ty * 4 + i;
        float4 o;
        int col = n0 + tx * 4;
        o.x = acc[i][0] + bi[col + 0];
        o.y = acc[i][1] + bi[col + 1];
        o.z = acc[i][2] + bi[col + 2];
        o.w = acc[i][3] + bi[col + 3];
        *reinterpret_cast<float4*>(&g_xg[(size_t)row * G3 + col]) = o;
    }
}

// ---------------------------------------------------------------------------
// Kernel 2: one GRU step (t).  For each (b,j) compute 3 dots of length H with
// gru_rk cols {j, j+H, j+2H}, then gate math.  grid (32 colgrp, 4 rowgrp),
// 256 thr, 2x2 micro-tile x 3 gates = 12 accumulators.
// ---------------------------------------------------------------------------
__global__ __launch_bounds__(256) void k_gru(
    int t, const float* __restrict__ rk, const float* __restrict__ br)
{
    __shared__ float Hs[32][33];    // [k][b]
    __shared__ float Rs[32][100];   // [k][g*32 + j]
    const float* __restrict__ hprev =
        (t == 0) ? g_hzero : (g_hs + (size_t)(t - 1) * Bb * Hh);
    float* __restrict__ hout = g_hs + (size_t)t * Bb * Hh;
    const float* __restrict__ xg_t = g_xg + (size_t)t * Bb * G3;

    const int j0 = blockIdx.x * 32;
    const int b0 = blockIdx.y * 32;
    const int tid = threadIdx.x;
    const int tx = tid & 15, ty = tid >> 4;
    const int h_b = tid >> 3, h_k4 = tid & 7;   // H-tile load: 32 rows x 8 float4
    const int r_k = tid >> 3, r_c4 = tid & 7;   // R-tile load

    float acc[3][2][2];
#pragma unroll
    for (int g = 0; g < 3; g++)
#pragma unroll
        for (int i = 0; i < 2; i++)
#pragma unroll
            for (int j = 0; j < 2; j++) acc[g][i][j] = 0.f;

    for (int k0 = 0; k0 < Hh; k0 += 32) {
        float4 hv = *reinterpret_cast<const float4*>(
            hprev + (size_t)(b0 + h_b) * Hh + k0 + h_k4 * 4);
        Hs[h_k4 * 4 + 0][h_b] = hv.x;
        Hs[h_k4 * 4 + 1][h_b] = hv.y;
        Hs[h_k4 * 4 + 2][h_b] = hv.z;
        Hs[h_k4 * 4 + 3][h_b] = hv.w;
#pragma unroll
        for (int g = 0; g < 3; g++) {
            float4 rv = *reinterpret_cast<const float4*>(
                rk + (size_t)(k0 + r_k) * G3 + g * Hh + j0 + r_c4 * 4);
            *reinterpret_cast<float4*>(&Rs[r_k][g * 32 + r_c4 * 4]) = rv;
        }
        __syncthreads();
#pragma unroll
        for (int kk = 0; kk < 32; kk++) {
            float h0 = Hs[kk][ty * 2 + 0];
            float h1 = Hs[kk][ty * 2 + 1];
#pragma unroll
            for (int g = 0; g < 3; g++) {
                float r0 = Rs[kk][g * 32 + tx * 2 + 0];
                float r1 = Rs[kk][g * 32 + tx * 2 + 1];
                acc[g][0][0] = fmaf(h0, r0, acc[g][0][0]);
                acc[g][0][1] = fmaf(h0, r1, acc[g][0][1]);
                acc[g][1][0] = fmaf(h1, r0, acc[g][1][0]);
                acc[g][1][1] = fmaf(h1, r1, acc[g][1][1]);
            }
        }
        __syncthreads();
    }

#pragma unroll
    for (int i = 0; i < 2; i++) {
        int b = b0 + ty * 2 + i;
#pragma unroll
        for (int jj = 0; jj < 2; jj++) {
            int j = j0 + tx * 2 + jj;
            float xz = xg_t[(size_t)b * G3 + j];
            float xr = xg_t[(size_t)b * G3 + Hh + j];
            float xh = xg_t[(size_t)b * G3 + 2 * Hh + j];
            float rz = acc[0][i][jj] + br[j];
            float rr = acc[1][i][jj] + br[Hh + j];
            float rh = acc[2][i][jj] + br[2 * Hh + j];
            float z = 1.f / (1.f + expf(-(xz + rz)));
            float rr_g = 1.f / (1.f + expf(-(xr + rr)));
            float hh = tanhf(xh + rr_g * rh);
            float hp = hprev[(size_t)b * Hh + j];
            hout[(size_t)b * Hh + j] = z * hp + (1.f - z) * hh;
        }
    }
}

// ---------------------------------------------------------------------------
// Kernel 3: d = relu(hs @ w1 + b1).  M=16384, N=128, K=1024.
// ---------------------------------------------------------------------------
__global__ __launch_bounds__(256) void k_w1relu(
    const float* __restrict__ w1, const float* __restrict__ b1)
{
    __shared__ float As[16][68];
    __shared__ float Bs[16][68];
    const int n0 = blockIdx.x * 64;
    const int m0 = blockIdx.y * 64;
    const int tid = threadIdx.x;
    const int tx = tid & 15, ty = tid >> 4;
    const int a_row = tid >> 2, a_c4 = tid & 3;
    const int b_row = tid >> 4, b_c4 = tid & 15;
    const float* __restrict__ apt = g_hs + (size_t)(m0 + a_row) * Hh;

    float acc[4][4];
#pragma unroll
    for (int i = 0; i < 4; i++)
#pragma unroll
        for (int j = 0; j < 4; j++) acc[i][j] = 0.f;

    for (int k0 = 0; k0 < Hh; k0 += 16) {
        float4 av = *reinterpret_cast<const float4*>(apt + k0 + a_c4 * 4);
        float4 bv = *reinterpret_cast<const float4*>(
            w1 + (size_t)(k0 + b_row) * Dd + n0 + b_c4 * 4);
        As[a_c4 * 4 + 0][a_row] = av.x;
        As[a_c4 * 4 + 1][a_row] = av.y;
        As[a_c4 * 4 + 2][a_row] = av.z;
        As[a_c4 * 4 + 3][a_row] = av.w;
        *reinterpret_cast<float4*>(&Bs[b_row][b_c4 * 4]) = bv;
        __syncthreads();
#pragma unroll
        for (int kk = 0; kk < 16; kk++) {
            float4 a = *reinterpret_cast<const float4*>(&As[kk][ty * 4]);
            float4 b = *reinterpret_cast<const float4*>(&Bs[kk][tx * 4]);
            float aa[4] = {a.x, a.y, a.z, a.w};
            float bb[4] = {b.x, b.y, b.z, b.w};
#pragma unroll
            for (int i = 0; i < 4; i++)
#pragma unroll
                for (int j = 0; j < 4; j++)
                    acc[i][j] = fmaf(aa[i], bb[j], acc[i][j]);
        }
        __syncthreads();
    }
#pragma unroll
    for (int i = 0; i < 4; i++) {
        int row = m0 + ty * 4 + i;
        int col = n0 + tx * 4;
        float4 o;
        o.x = fmaxf(acc[i][0] + b1[col + 0], 0.f);
        o.y = fmaxf(acc[i][1] + b1[col + 1], 0.f);
        o.z = fmaxf(acc[i][2] + b1[col + 2], 0.f);
        o.w = fmaxf(acc[i][3] + b1[col + 3], 0.f);
        *reinterpret_cast<float4*>(&g_d[(size_t)row * Dd + col]) = o;
    }
}

// ---------------------------------------------------------------------------
// Kernel 4: logits = d @ w2 + b2 -> d_out (as [B][T][V]).  M=16384, N=10000, K=128.
// ---------------------------------------------------------------------------
__global__ __launch_bounds__(256) void k_w2(
    const float* __restrict__ w2, const float* __restrict__ b2,
    float* __restrict__ out)
{
    __shared__ float As[16][68];
    __shared__ float Bs[16][68];
    const int n0 = blockIdx.x * 64;
    const int m0 = blockIdx.y * 64;
    const int tid = threadIdx.x;
    const int tx = tid & 15, ty = tid >> 4;
    const int a_row = tid >> 2, a_c4 = tid & 3;
    const int b_row = tid >> 4, b_c4 = tid & 15;
    const float* __restrict__ apt = g_d + (size_t)(m0 + a_row) * Dd;
    const bool full = (n0 + 64 <= Vv);

    float acc[4][4];
#pragma unroll
    for (int i = 0; i < 4; i++)
#pragma unroll
        for (int j = 0; j < 4; j++) acc[i][j] = 0.f;

    for (int k0 = 0; k0 < Dd; k0 += 16) {
        float4 av = *reinterpret_cast<const float4*>(apt + k0 + a_c4 * 4);
        As[a_c4 * 4 + 0][a_row] = av.x;
        As[a_c4 * 4 + 1][a_row] = av.y;
        As[a_c4 * 4 + 2][a_row] = av.z;
        As[a_c4 * 4 + 3][a_row] = av.w;
        if (full) {
            float4 bv = *reinterpret_cast<const float4*>(
                w2 + (size_t)(k0 + b_row) * Vv + n0 + b_c4 * 4);
            *reinterpret_cast<float4*>(&Bs[b_row][b_c4 * 4]) = bv;
        } else {
#pragma unroll
            for (int c = 0; c < 4; c++) {
                int col = n0 + b_c4 * 4 + c;
                Bs[b_row][b_c4 * 4 + c] =
                    (col < Vv) ? w2[(size_t)(k0 + b_row) * Vv + col] : 0.f;
            }
        }
        __syncthreads();
#pragma unroll
        for (int kk = 0; kk < 16; kk++) {
            float4 a = *reinterpret_cast<const float4*>(&As[kk][ty * 4]);
            float4 b = *reinterpret_cast<const float4*>(&Bs[kk][tx * 4]);
            float aa[4] = {a.x, a.y, a.z, a.w};
            float bb[4] = {b.x, b.y, b.z, b.w};
#pragma unroll
            for (int i = 0; i < 4; i++)
#pragma unroll
                for (int j = 0; j < 4; j++)
                    acc[i][j] = fmaf(aa[i], bb[j], acc[i][j]);
        }
        __syncthreads();
    }
#pragma unroll
    for (int i = 0; i < 4; i++) {
        int rr = m0 + ty * 4 + i;           // rr = t*B + b
        int t = rr >> 7, b = rr & 127;
        size_t obase = ((size_t)b * Tt + t) * Vv;
#pragma unroll
        for (int j = 0; j < 4; j++) {
            int col = n0 + tx * 4 + j;
            if (col < Vv) out[obase + col] = acc[i][j] + b2[col];
        }
    }
}

// ---------------------------------------------------------------------------
// Kernel 5: in-place softmax over rows of 10000, with logits*50 (TEMP=0.02).
// One block per row; row lives in registers (40/thread).
// ---------------------------------------------------------------------------
__global__ __launch_bounds__(256) void k_softmax(float* __restrict__ out)
{
    float* __restrict__ p = out + (size_t)blockIdx.x * Vv;
    const int tid = threadIdx.x;
    float vals[40];
    float mx = -1e30f;
#pragma unroll
    for (int i = 0; i < 40; i++) {
        int idx = tid + (i << 8);
        if (idx < Vv) {
            float v = p[idx] * 50.0f;
            vals[i] = v;
            mx = fmaxf(mx, v);
        } else {
            vals[i] = -1e30f;
        }
    }
    __shared__ float redm[8];
    __shared__ float reds[8];
#pragma unroll
    for (int o = 16; o; o >>= 1) mx = fmaxf(mx, __shfl_xor_sync(0xffffffffu, mx, o));
    if ((tid & 31) == 0) redm[tid >> 5] = mx;
    __syncthreads();
    mx = redm[0];
#pragma unroll
    for (int w = 1; w < 8; w++) mx = fmaxf(mx, redm[w]);

    float s = 0.f;
#pragma unroll
    for (int i = 0; i < 40; i++) {
        int idx = tid + (i << 8);
        if (idx < Vv) {
            float e = expf(vals[i] - mx);
            vals[i] = e;
            s += e;
        }
    }
#pragma unroll
    for (int o = 16; o; o >>= 1) s += __shfl_xor_sync(0xffffffffu, s, o);
    if ((tid & 31) == 0) reds[tid >> 5] = s;
    __syncthreads();
    float tot = 0.f;
#pragma unroll
    for (int w = 0; w < 8; w++) tot += reds[w];
    float inv = 1.0f / tot;
#pragma unroll
    for (int i = 0; i < 40; i++) {
        int idx = tid + (i << 8);
        if (idx < Vv) p[idx] = vals[i] * inv;
    }
}

// ---------------------------------------------------------------------------
extern "C" void kernel_launch(void* const* d_in, const int* in_sizes, int n_in,
                              void* d_out, int out_size)
{
    const int*   tokens = (const int*)  d_in[0];
    const float* emb    = (const float*)d_in[1];
    const float* gk     = (const float*)d_in[2];
    const float* grk    = (const float*)d_in[3];
    const float* gbi    = (const float*)d_in[4];
    const float* gbr    = (const float*)d_in[5];
    const float* w1     = (const float*)d_in[6];
    const float* b1     = (const float*)d_in[7];
    const float* w2     = (const float*)d_in[8];
    const float* b2     = (const float*)d_in[9];
    float* out = (float*)d_out;

    dim3 blk(256);
    k_embed_gemm<<<dim3(G3 / 64, MROWS / 64), blk>>>(tokens, emb, gk, gbi);
    for (int t = 0; t < Tt; t++)
        k_gru<<<dim3(32, 4), blk>>>(t, grk, gbr);
    k_w1relu<<<dim3(Dd / 64, MROWS / 64), blk>>>(w1, b1);
    k_w2<<<dim3((Vv + 63) / 64, MROWS / 64), blk>>>(w2, b2, out);
    k_softmax<<<MROWS, blk>>>(out);
}

// round 2
// speedup vs baseline: 1.2779x; 1.2779x over previous
#include <cuda_runtime.h>
#include <math.h>

#define Bb 128
#define Tt 128
#define Vv 10000
#define Ee 256
#define Hh 1024
#define Dd 128
#define G3 3072           // 3*H
#define MROWS (Bb*Tt)     // 16384
#define GRU_CTAS 128

// Scratch (static __device__ globals: allowed; zero-initialized at load)
__device__ float g_xg[MROWS * G3];     // [T][B][3H]  input-side gate pre-activations (incl. bi)
__device__ float g_hs[MROWS * Hh];     // [T][B][H]   hidden states per step
__device__ float g_d [MROWS * Dd];     // [T][B][D]   relu(hs@w1+b1)
__device__ float g_hzero[Bb * Hh];     // stays all-zero: h_{-1}
__device__ unsigned g_bar;             // grid barrier counter (reset by k_reset each call)

__global__ void k_reset() { g_bar = 0u; }

// ---------------------------------------------------------------------------
// Kernel 1: xg[t*B+b][:] = emb[tokens[b][t]] @ gru_k + gru_bi
// M=16384, N=3072, K=256.  64x64 tile, BK=16, 256 thr, 4x4 micro-tile.
// ---------------------------------------------------------------------------
__global__ __launch_bounds__(256) void k_embed_gemm(
    const int* __restrict__ tokens, const float* __restrict__ emb,
    const float* __restrict__ gk, const float* __restrict__ bi)
{
    __shared__ float As[16][68];   // [k][m]
    __shared__ float Bs[16][68];   // [k][n]
    const int n0 = blockIdx.x * 64;
    const int m0 = blockIdx.y * 64;
    const int tid = threadIdx.x;
    const int tx = tid & 15, ty = tid >> 4;
    const int a_row = tid >> 2, a_c4 = tid & 3;
    const int b_row = tid >> 4, b_c4 = tid & 15;
    const int r = m0 + a_row;                       // r = t*B + b
    const int tok = tokens[(r & 127) * Tt + (r >> 7)];   // tokens[b][t]
    const float4* __restrict__ apt =
        reinterpret_cast<const float4*>(emb + (size_t)tok * Ee);

    float acc[4][4];
#pragma unroll
    for (int i = 0; i < 4; i++)
#pragma unroll
        for (int j = 0; j < 4; j++) acc[i][j] = 0.f;

    for (int k0 = 0; k0 < Ee; k0 += 16) {
        float4 av = apt[(k0 >> 2) + a_c4];
        float4 bv = *reinterpret_cast<const float4*>(
            gk + (size_t)(k0 + b_row) * G3 + n0 + b_c4 * 4);
        As[a_c4 * 4 + 0][a_row] = av.x;
        As[a_c4 * 4 + 1][a_row] = av.y;
        As[a_c4 * 4 + 2][a_row] = av.z;
        As[a_c4 * 4 + 3][a_row] = av.w;
        *reinterpret_cast<float4*>(&Bs[b_row][b_c4 * 4]) = bv;
        __syncthreads();
#pragma unroll
        for (int kk = 0; kk < 16; kk++) {
            float4 a = *reinterpret_cast<const float4*>(&As[kk][ty * 4]);
            float4 b = *reinterpret_cast<const float4*>(&Bs[kk][tx * 4]);
            float aa[4] = {a.x, a.y, a.z, a.w};
            float bb[4] = {b.x, b.y, b.z, b.w};
#pragma unroll
            for (int i = 0; i < 4; i++)
#pragma unroll
                for (int j = 0; j < 4; j++)
                    acc[i][j] = fmaf(aa[i], bb[j], acc[i][j]);
        }
        __syncthreads();
    }
#pragma unroll
    for (int i = 0; i < 4; i++) {
        int row = m0 + ty * 4 + i;
        float4 o;
        int col = n0 + tx * 4;
        o.x = acc[i][0] + bi[col + 0];
        o.y = acc[i][1] + bi[col + 1];
        o.z = acc[i][2] + bi[col + 2];
        o.w = acc[i][3] + bi[col + 3];
        *reinterpret_cast<float4*>(&g_xg[(size_t)row * G3 + col]) = o;
    }
}

// ---------------------------------------------------------------------------
// Kernel 2: persistent GRU. One launch; 128 co-resident CTAs; software grid
// barrier between the 128 time steps.
// CTA tile: 32 b-rows x 32 j-cols x 3 gates.  blockIdx: (bx&31)->j0, (bx>>5)->b0.
// Thread micro-tile: 4b x 1j x 3g = 12 accumulators.
// Shared double-buffered: Hs[2][32b][36] ([b][k], pad->float4-aligned),
//                         Rs[2][32k][100] ([k][g*32+j], pad->conflict-free).
// Inner loop per 4 k: 4x LDS.128 (warp-broadcast h) + 12x LDS.32 (r) + 48 FFMA.
// ---------------------------------------------------------------------------
__global__ __launch_bounds__(256) void k_gru_persist(
    const float* __restrict__ rk, const float* __restrict__ br)
{
    __shared__ float Hs[2][32][36];
    __shared__ float Rs[2][32][100];

    const int tid = threadIdx.x;
    const int j0 = (blockIdx.x & 31) * 32;
    const int b0 = (blockIdx.x >> 5) * 32;
    const int tx  = tid & 31;       // j within tile
    const int tyg = tid >> 5;       // 0..7 -> b-group of 4
    // loader indices
    const int lb = tid >> 3;        // 0..31: b row for H tile
    const int lk = tid & 7;         // float4 index along k (8 per 32)
    const int rkrow = tid >> 3;     // 0..31: k row for R tile
    const int rj = tid & 7;         // float4 index along j (8 per 32)

    const int jj = j0 + tx;
    const float brz = br[jj];
    const float brr = br[Hh + jj];
    const float brh = br[2 * Hh + jj];

    for (int t = 0; t < Tt; t++) {
        const float* __restrict__ hprev =
            (t == 0) ? g_hzero : (g_hs + (size_t)(t - 1) * Bb * Hh);
        float* __restrict__ hout = g_hs + (size_t)t * Bb * Hh;
        const float* __restrict__ xg_t = g_xg + (size_t)t * Bb * G3;

        float acc[3][4];
#pragma unroll
        for (int g = 0; g < 3; g++)
#pragma unroll
            for (int i = 0; i < 4; i++) acc[g][i] = 0.f;

        // prefetch k-tile 0
        float4 hv = *reinterpret_cast<const float4*>(
            hprev + (size_t)(b0 + lb) * Hh + lk * 4);
        float4 rv0 = *reinterpret_cast<const float4*>(
            rk + (size_t)rkrow * G3 + j0 + rj * 4);
        float4 rv1 = *reinterpret_cast<const float4*>(
            rk + (size_t)rkrow * G3 + Hh + j0 + rj * 4);
        float4 rv2 = *reinterpret_cast<const float4*>(
            rk + (size_t)rkrow * G3 + 2 * Hh + j0 + rj * 4);
        *reinterpret_cast<float4*>(&Hs[0][lb][lk * 4]) = hv;
        *reinterpret_cast<float4*>(&Rs[0][rkrow][rj * 4])      = rv0;
        *reinterpret_cast<float4*>(&Rs[0][rkrow][32 + rj * 4]) = rv1;
        *reinterpret_cast<float4*>(&Rs[0][rkrow][64 + rj * 4]) = rv2;
        __syncthreads();

        for (int kt = 0; kt < 32; kt++) {
            const int cur = kt & 1;
            const int nxt = cur ^ 1;
            const bool more = (kt < 31);
            if (more) {
                const int k0 = (kt + 1) * 32;
                hv = *reinterpret_cast<const float4*>(
                    hprev + (size_t)(b0 + lb) * Hh + k0 + lk * 4);
                rv0 = *reinterpret_cast<const float4*>(
                    rk + (size_t)(k0 + rkrow) * G3 + j0 + rj * 4);
                rv1 = *reinterpret_cast<const float4*>(
                    rk + (size_t)(k0 + rkrow) * G3 + Hh + j0 + rj * 4);
                rv2 = *reinterpret_cast<const float4*>(
                    rk + (size_t)(k0 + rkrow) * G3 + 2 * Hh + j0 + rj * 4);
            }
#pragma unroll
            for (int kk = 0; kk < 32; kk += 4) {
                float4 ha = *reinterpret_cast<const float4*>(&Hs[cur][tyg * 4 + 0][kk]);
                float4 hb = *reinterpret_cast<const float4*>(&Hs[cur][tyg * 4 + 1][kk]);
                float4 hc = *reinterpret_cast<const float4*>(&Hs[cur][tyg * 4 + 2][kk]);
                float4 hd = *reinterpret_cast<const float4*>(&Hs[cur][tyg * 4 + 3][kk]);
                float hav[4] = {ha.x, ha.y, ha.z, ha.w};
                float hbv[4] = {hb.x, hb.y, hb.z, hb.w};
                float hcv[4] = {hc.x, hc.y, hc.z, hc.w};
                float hdv[4] = {hd.x, hd.y, hd.z, hd.w};
#pragma unroll
                for (int q = 0; q < 4; q++) {
                    float rz = Rs[cur][kk + q][tx];
                    float rr = Rs[cur][kk + q][32 + tx];
                    float rh = Rs[cur][kk + q][64 + tx];
                    acc[0][0] = fmaf(hav[q], rz, acc[0][0]);
                    acc[0][1] = fmaf(hbv[q], rz, acc[0][1]);
                    acc[0][2] = fmaf(hcv[q], rz, acc[0][2]);
                    acc[0][3] = fmaf(hdv[q], rz, acc[0][3]);
                    acc[1][0] = fmaf(hav[q], rr, acc[1][0]);
                    acc[1][1] = fmaf(hbv[q], rr, acc[1][1]);
                    acc[1][2] = fmaf(hcv[q], rr, acc[1][2]);
                    acc[1][3] = fmaf(hdv[q], rr, acc[1][3]);
                    acc[2][0] = fmaf(hav[q], rh, acc[2][0]);
                    acc[2][1] = fmaf(hbv[q], rh, acc[2][1]);
                    acc[2][2] = fmaf(hcv[q], rh, acc[2][2]);
                    acc[2][3] = fmaf(hdv[q], rh, acc[2][3]);
                }
            }
            if (more) {
                *reinterpret_cast<float4*>(&Hs[nxt][lb][lk * 4]) = hv;
                *reinterpret_cast<float4*>(&Rs[nxt][rkrow][rj * 4])      = rv0;
                *reinterpret_cast<float4*>(&Rs[nxt][rkrow][32 + rj * 4]) = rv1;
                *reinterpret_cast<float4*>(&Rs[nxt][rkrow][64 + rj * 4]) = rv2;
            }
            __syncthreads();
        }

        // epilogue: gate math + write h_t
#pragma unroll
        for (int i = 0; i < 4; i++) {
            const int b = b0 + tyg * 4 + i;
            const float xz = xg_t[(size_t)b * G3 + jj];
            const float xr = xg_t[(size_t)b * G3 + Hh + jj];
            const float xh = xg_t[(size_t)b * G3 + 2 * Hh + jj];
            const float z  = 1.f / (1.f + expf(-(xz + acc[0][i] + brz)));
            const float rg = 1.f / (1.f + expf(-(xr + acc[1][i] + brr)));
            const float hh = tanhf(xh + rg * (acc[2][i] + brh));
            const float hp = hprev[(size_t)b * Hh + jj];
            hout[(size_t)b * Hh + jj] = z * hp + (1.f - z) * hh;
        }

        // grid barrier (release h_t, wait for all CTAs)
        __threadfence();
        __syncthreads();
        if (tid == 0) {
            const unsigned target = (unsigned)(t + 1) * GRU_CTAS;
            atomicAdd(&g_bar, 1u);
            while (*reinterpret_cast<volatile unsigned*>(&g_bar) < target) { }
        }
        __syncthreads();
    }
}

// ---------------------------------------------------------------------------
// Kernel 3: d = relu(hs @ w1 + b1).  M=16384, N=128, K=1024.
// ---------------------------------------------------------------------------
__global__ __launch_bounds__(256) void k_w1relu(
    const float* __restrict__ w1, const float* __restrict__ b1)
{
    __shared__ float As[16][68];
    __shared__ float Bs[16][68];
    const int n0 = blockIdx.x * 64;
    const int m0 = blockIdx.y * 64;
    const int tid = threadIdx.x;
    const int tx = tid & 15, ty = tid >> 4;
    const int a_row = tid >> 2, a_c4 = tid & 3;
    const int b_row = tid >> 4, b_c4 = tid & 15;
    const float* __restrict__ apt = g_hs + (size_t)(m0 + a_row) * Hh;

    float acc[4][4];
#pragma unroll
    for (int i = 0; i < 4; i++)
#pragma unroll
        for (int j = 0; j < 4; j++) acc[i][j] = 0.f;

    for (int k0 = 0; k0 < Hh; k0 += 16) {
        float4 av = *reinterpret_cast<const float4*>(apt + k0 + a_c4 * 4);
        float4 bv = *reinterpret_cast<const float4*>(
            w1 + (size_t)(k0 + b_row) * Dd + n0 + b_c4 * 4);
        As[a_c4 * 4 + 0][a_row] = av.x;
        As[a_c4 * 4 + 1][a_row] = av.y;
        As[a_c4 * 4 + 2][a_row] = av.z;
        As[a_c4 * 4 + 3][a_row] = av.w;
        *reinterpret_cast<float4*>(&Bs[b_row][b_c4 * 4]) = bv;
        __syncthreads();
#pragma unroll
        for (int kk = 0; kk < 16; kk++) {
            float4 a = *reinterpret_cast<const float4*>(&As[kk][ty * 4]);
            float4 b = *reinterpret_cast<const float4*>(&Bs[kk][tx * 4]);
            float aa[4] = {a.x, a.y, a.z, a.w};
            float bb[4] = {b.x, b.y, b.z, b.w};
#pragma unroll
            for (int i = 0; i < 4; i++)
#pragma unroll
                for (int j = 0; j < 4; j++)
                    acc[i][j] = fmaf(aa[i], bb[j], acc[i][j]);
        }
        __syncthreads();
    }
#pragma unroll
    for (int i = 0; i < 4; i++) {
        int row = m0 + ty * 4 + i;
        int col = n0 + tx * 4;
        float4 o;
        o.x = fmaxf(acc[i][0] + b1[col + 0], 0.f);
        o.y = fmaxf(acc[i][1] + b1[col + 1], 0.f);
        o.z = fmaxf(acc[i][2] + b1[col + 2], 0.f);
        o.w = fmaxf(acc[i][3] + b1[col + 3], 0.f);
        *reinterpret_cast<float4*>(&g_d[(size_t)row * Dd + col]) = o;
    }
}

// ---------------------------------------------------------------------------
// Kernel 4: logits = d @ w2 + b2 -> d_out (as [B][T][V]).  M=16384, N=10000, K=128.
// ---------------------------------------------------------------------------
__global__ __launch_bounds__(256) void k_w2(
    const float* __restrict__ w2, const float* __restrict__ b2,
    float* __restrict__ out)
{
    __shared__ float As[16][68];
    __shared__ float Bs[16][68];
    const int n0 = blockIdx.x * 64;
    const int m0 = blockIdx.y * 64;
    const int tid = threadIdx.x;
    const int tx = tid & 15, ty = tid >> 4;
    const int a_row = tid >> 2, a_c4 = tid & 3;
    const int b_row = tid >> 4, b_c4 = tid & 15;
    const float* __restrict__ apt = g_d + (size_t)(m0 + a_row) * Dd;
    const bool full = (n0 + 64 <= Vv);

    float acc[4][4];
#pragma unroll
    for (int i = 0; i < 4; i++)
#pragma unroll
        for (int j = 0; j < 4; j++) acc[i][j] = 0.f;

    for (int k0 = 0; k0 < Dd; k0 += 16) {
        float4 av = *reinterpret_cast<const float4*>(apt + k0 + a_c4 * 4);
        As[a_c4 * 4 + 0][a_row] = av.x;
        As[a_c4 * 4 + 1][a_row] = av.y;
        As[a_c4 * 4 + 2][a_row] = av.z;
        As[a_c4 * 4 + 3][a_row] = av.w;
        if (full) {
            float4 bv = *reinterpret_cast<const float4*>(
                w2 + (size_t)(k0 + b_row) * Vv + n0 + b_c4 * 4);
            *reinterpret_cast<float4*>(&Bs[b_row][b_c4 * 4]) = bv;
        } else {
#pragma unroll
            for (int c = 0; c < 4; c++) {
                int col = n0 + b_c4 * 4 + c;
                Bs[b_row][b_c4 * 4 + c] =
                    (col < Vv) ? w2[(size_t)(k0 + b_row) * Vv + col] : 0.f;
            }
        }
        __syncthreads();
#pragma unroll
        for (int kk = 0; kk < 16; kk++) {
            float4 a = *reinterpret_cast<const float4*>(&As[kk][ty * 4]);
            float4 b = *reinterpret_cast<const float4*>(&Bs[kk][tx * 4]);
            float aa[4] = {a.x, a.y, a.z, a.w};
            float bb[4] = {b.x, b.y, b.z, b.w};
#pragma unroll
            for (int i = 0; i < 4; i++)
#pragma unroll
                for (int j = 0; j < 4; j++)
                    acc[i][j] = fmaf(aa[i], bb[j], acc[i][j]);
        }
        __syncthreads();
    }
#pragma unroll
    for (int i = 0; i < 4; i++) {
        int rr = m0 + ty * 4 + i;           // rr = t*B + b
        int t = rr >> 7, b = rr & 127;
        size_t obase = ((size_t)b * Tt + t) * Vv;
#pragma unroll
        for (int j = 0; j < 4; j++) {
            int col = n0 + tx * 4 + j;
            if (col < Vv) out[obase + col] = acc[i][j] + b2[col];
        }
    }
}

// ---------------------------------------------------------------------------
// Kernel 5: in-place softmax over rows of 10000, with logits*50 (TEMP=0.02).
// ---------------------------------------------------------------------------
__global__ __launch_bounds__(256) void k_softmax(float* __restrict__ out)
{
    float* __restrict__ p = out + (size_t)blockIdx.x * Vv;
    const int tid = threadIdx.x;
    float vals[40];
    float mx = -1e30f;
#pragma unroll
    for (int i = 0; i < 40; i++) {
        int idx = tid + (i << 8);
        if (idx < Vv) {
            float v = p[idx] * 50.0f;
            vals[i] = v;
            mx = fmaxf(mx, v);
        } else {
            vals[i] = -1e30f;
        }
    }
    __shared__ float redm[8];
    __shared__ float reds[8];
#pragma unroll
    for (int o = 16; o; o >>= 1) mx = fmaxf(mx, __shfl_xor_sync(0xffffffffu, mx, o));
    if ((tid & 31) == 0) redm[tid >> 5] = mx;
    __syncthreads();
    mx = redm[0];
#pragma unroll
    for (int w = 1; w < 8; w++) mx = fmaxf(mx, redm[w]);

    float s = 0.f;
#pragma unroll
    for (int i = 0; i < 40; i++) {
        int idx = tid + (i << 8);
        if (idx < Vv) {
            float e = expf(vals[i] - mx);
            vals[i] = e;
            s += e;
        }
    }
#pragma unroll
    for (int o = 16; o; o >>= 1) s += __shfl_xor_sync(0xffffffffu, s, o);
    if ((tid & 31) == 0) reds[tid >> 5] = s;
    __syncthreads();
    float tot = 0.f;
#pragma unroll
    for (int w = 0; w < 8; w++) tot += reds[w];
    float inv = 1.0f / tot;
#pragma unroll
    for (int i = 0; i < 40; i++) {
        int idx = tid + (i << 8);
        if (idx < Vv) p[idx] = vals[i] * inv;
    }
}

// ---------------------------------------------------------------------------
extern "C" void kernel_launch(void* const* d_in, const int* in_sizes, int n_in,
                              void* d_out, int out_size)
{
    const int*   tokens = (const int*)  d_in[0];
    const float* emb    = (const float*)d_in[1];
    const float* gk     = (const float*)d_in[2];
    const float* grk    = (const float*)d_in[3];
    const float* gbi    = (const float*)d_in[4];
    const float* gbr    = (const float*)d_in[5];
    const float* w1     = (const float*)d_in[6];
    const float* b1     = (const float*)d_in[7];
    const float* w2     = (const float*)d_in[8];
    const float* b2     = (const float*)d_in[9];
    float* out = (float*)d_out;

    dim3 blk(256);
    k_reset<<<1, 1>>>();
    k_embed_gemm<<<dim3(G3 / 64, MROWS / 64), blk>>>(tokens, emb, gk, gbi);
    k_gru_persist<<<GRU_CTAS, blk>>>(grk, gbr);
    k_w1relu<<<dim3(Dd / 64, MROWS / 64), blk>>>(w1, b1);
    k_w2<<<dim3((Vv + 63) / 64, MROWS / 64), blk>>>(w2, b2, out);
    k_softmax<<<MROWS, blk>>>(out);
}

// round 4
// speedup vs baseline: 1.3225x; 1.0348x over previous
#include <cuda_runtime.h>
#include <cuda_bf16.h>
#include <math.h>
#include <stdint.h>

#define Bb 128
#define Tt 128
#define Vv 10000
#define Ee 256
#define Hh 1024
#define Dd 128
#define G3 3072           // 3*H
#define MROWS (Bb*Tt)     // 16384
#define GRID_GRU 96       // 24 n-tiles x 4 k-splits

// ---------------- scratch (__device__ globals: allowed) --------------------
__device__ float g_xg[MROWS * G3];       // [T][B][3H] input-side preacts (incl bi)
__device__ float g_hs[MROWS * Hh];       // [T][B][H]
__device__ float g_d [MROWS * Dd];
__device__ float g_rgp[4 * Bb * G3];     // recurrent matmul partials per k-split
__device__ __nv_bfloat16 g_rkT_hi[G3 * Hh];  // rk^T split hi  [n][k]
__device__ __nv_bfloat16 g_rkT_lo[G3 * Hh];  // rk^T split lo
__device__ __nv_bfloat16 g_hhi[Bb * Hh];     // h_t split hi [b][k]
__device__ __nv_bfloat16 g_hlo[Bb * Hh];     // h_t split lo
__device__ unsigned g_bar;

__global__ void k_reset() { g_bar = 0u; }

// ---------------- PTX helpers (baseline ISA only: sm_80-class) -------------
__device__ __forceinline__ uint32_t smem_to_u32(const void* p) {
    uint32_t a;
    asm("{ .reg .u64 t; cvta.to.shared.u64 t, %1; cvt.u32.u64 %0, t; }"
        : "=r"(a) : "l"(p));
    return a;
}
__device__ __forceinline__ void ldsm_x4(uint32_t* r, uint32_t addr) {
    asm volatile("ldmatrix.sync.aligned.m8n8.x4.shared.b16 {%0,%1,%2,%3}, [%4];"
        : "=r"(r[0]), "=r"(r[1]), "=r"(r[2]), "=r"(r[3]) : "r"(addr));
}
__device__ __forceinline__ void mma_16816(float* d, const uint32_t* a, const uint32_t* b) {
    asm volatile("mma.sync.aligned.m16n8k16.row.col.f32.bf16.bf16.f32 "
        "{%0,%1,%2,%3}, {%4,%5,%6,%7}, {%8,%9}, {%0,%1,%2,%3};"
        : "+f"(d[0]), "+f"(d[1]), "+f"(d[2]), "+f"(d[3])
        : "r"(a[0]), "r"(a[1]), "r"(a[2]), "r"(a[3]), "r"(b[0]), "r"(b[1]));
}
__device__ __forceinline__ void cp16(uint32_t dst, const void* src) {
    asm volatile("cp.async.cg.shared.global [%0], [%1], 16;" :: "r"(dst), "l"(src));
}
#define CP_COMMIT() asm volatile("cp.async.commit_group;" ::: "memory")
#define CP_WAIT(n)  asm volatile("cp.async.wait_group %0;" :: "n"(n) : "memory")

__device__ __forceinline__ float sig_(float x) { return 1.f / (1.f + expf(-x)); }

// SMEM tile geometry: 128 rows x 64 bf16, rows padded to 72 bf16 = 144 B
#define ROWB 144
#define TILEB 18432          // 128*144
#define BUFB  (4*TILEB)      // Ah, Al, Bh, Bl
#define GRU_SMEM (2*BUFB)    // double buffered = 147456 B

// ---------------------------------------------------------------------------
// init: split + transpose rk [K=1024][N=3072] -> rkT hi/lo [N=3072][K=1024]
// ---------------------------------------------------------------------------
__global__ __launch_bounds__(256) void k_rk_split(const float* __restrict__ rk)
{
    __shared__ float tile[32][33];
    const int n0 = blockIdx.x * 32, k0 = blockIdx.y * 32;
    const int tx = threadIdx.x & 31, ty = threadIdx.x >> 5;  // ty 0..7
#pragma unroll
    for (int i = 0; i < 4; i++)
        tile[ty + 8 * i][tx] = rk[(size_t)(k0 + ty + 8 * i) * G3 + n0 + tx];
    __syncthreads();
#pragma unroll
    for (int i = 0; i < 4; i++) {
        int n = n0 + ty + 8 * i;
        float v = tile[tx][ty + 8 * i];
        __nv_bfloat16 hi = __float2bfloat16(v);
        __nv_bfloat16 lo = __float2bfloat16(v - __bfloat162float(hi));
        g_rkT_hi[(size_t)n * Hh + k0 + tx] = hi;
        g_rkT_lo[(size_t)n * Hh + k0 + tx] = lo;
    }
}

// ---------------------------------------------------------------------------
// Kernel 1: xg = emb[tokens] @ gru_k + gru_bi   (fp32)
// ---------------------------------------------------------------------------
__global__ __launch_bounds__(256) void k_embed_gemm(
    const int* __restrict__ tokens, const float* __restrict__ emb,
    const float* __restrict__ gk, const float* __restrict__ bi)
{
    __shared__ float As[16][68];
    __shared__ float Bs[16][68];
    const int n0 = blockIdx.x * 64;
    const int m0 = blockIdx.y * 64;
    const int tid = threadIdx.x;
    const int tx = tid & 15, ty = tid >> 4;
    const int a_row = tid >> 2, a_c4 = tid & 3;
    const int b_row = tid >> 4, b_c4 = tid & 15;
    const int r = m0 + a_row;
    const int tok = tokens[(r & 127) * Tt + (r >> 7)];
    const float4* __restrict__ apt =
        reinterpret_cast<const float4*>(emb + (size_t)tok * Ee);

    float acc[4][4];
#pragma unroll
    for (int i = 0; i < 4; i++)
#pragma unroll
        for (int j = 0; j < 4; j++) acc[i][j] = 0.f;

    for (int k0 = 0; k0 < Ee; k0 += 16) {
        float4 av = apt[(k0 >> 2) + a_c4];
        float4 bv = *reinterpret_cast<const float4*>(
            gk + (size_t)(k0 + b_row) * G3 + n0 + b_c4 * 4);
        As[a_c4 * 4 + 0][a_row] = av.x;
        As[a_c4 * 4 + 1][a_row] = av.y;
        As[a_c4 * 4 + 2][a_row] = av.z;
        As[a_c4 * 4 + 3][a_row] = av.w;
        *reinterpret_cast<float4*>(&Bs[b_row][b_c4 * 4]) = bv;
        __syncthreads();
#pragma unroll
        for (int kk = 0; kk < 16; kk++) {
            float4 a = *reinterpret_cast<const float4*>(&As[kk][ty * 4]);
            float4 b = *reinterpret_cast<const float4*>(&Bs[kk][tx * 4]);
            float aa[4] = {a.x, a.y, a.z, a.w};
            float bb[4] = {b.x, b.y, b.z, b.w};
#pragma unroll
            for (int i = 0; i < 4; i++)
#pragma unroll
                for (int j = 0; j < 4; j++)
                    acc[i][j] = fmaf(aa[i], bb[j], acc[i][j]);
        }
        __syncthreads();
    }
#pragma unroll
    for (int i = 0; i < 4; i++) {
        int row = m0 + ty * 4 + i;
        float4 o;
        int col = n0 + tx * 4;
        o.x = acc[i][0] + bi[col + 0];
        o.y = acc[i][1] + bi[col + 1];
        o.z = acc[i][2] + bi[col + 2];
        o.w = acc[i][3] + bi[col + 3];
        *reinterpret_cast<float4*>(&g_xg[(size_t)row * G3 + col]) = o;
    }
}

// ---------------------------------------------------------------------------
// Kernel 2: persistent GRU with mma.sync bf16 (3-pass split for fp32 accuracy)
// 96 CTAs = 24 n-tiles(128) x 4 k-splits(256).
// ---------------------------------------------------------------------------
__global__ __launch_bounds__(256, 1) void k_gru_mma(const float* __restrict__ br)
{
    extern __shared__ char smem[];
    const uint32_t sb = smem_to_u32(smem);
    const int tid = threadIdx.x;
    const int lane = tid & 31;
    const int wid = tid >> 5;
    const int ntile = blockIdx.x % 24;
    const int ks    = blockIdx.x / 24;       // 0..3
    const int n0    = ntile * 128;
    const int kbase = ks * 256;
    const int mbase = (wid & 3) * 32;        // warp M rows (batch)
    const int nbase = (wid >> 2) * 64;       // warp N cols within tile

    // loader geometry
    const int lrow = tid >> 3;               // 0..31 (+32*i)
    const int lg   = tid & 7;                // 16B group
    // ldmatrix per-thread offsets
    const uint32_t aoff = (uint32_t)((lane & 15) * ROWB + ((lane >> 4) & 1) * 16);
    const uint32_t boff = (uint32_t)((((lane & 7) + ((lane >> 4) & 1) * 8)) * ROWB
                                     + ((lane >> 3) & 1) * 16);

    unsigned epoch = 0;

    for (int t = 0; t < Tt; t++) {
        if (t > 0) {
            // ---------------- phase A ----------------
            float accs[64];
#pragma unroll
            for (int i = 0; i < 64; i++) accs[i] = 0.f;

            // issue chunk 0 and 1 loads
#pragma unroll
            for (int c = 0; c < 2; c++) {
                const int kcur = kbase + c * 64;
                const uint32_t base = sb + c * BUFB;
#pragma unroll
                for (int i = 0; i < 4; i++) {
                    const int row = lrow + 32 * i;
                    const uint32_t d = base + row * ROWB + lg * 16;
                    const size_t ea = ((size_t)row * Hh + kcur + lg * 8) * 2;
                    cp16(d,             (const char*)g_hhi + ea);
                    cp16(d + TILEB,     (const char*)g_hlo + ea);
                    const size_t eb = ((size_t)(n0 + row) * Hh + kcur + lg * 8) * 2;
                    cp16(d + 2 * TILEB, (const char*)g_rkT_hi + eb);
                    cp16(d + 3 * TILEB, (const char*)g_rkT_lo + eb);
                }
                CP_COMMIT();
            }

#pragma unroll
            for (int c = 0; c < 4; c++) {
                if (c < 3) { CP_WAIT(1); } else { CP_WAIT(0); }
                __syncthreads();
                const uint32_t bufA = sb + (c & 1) * BUFB;
                // compute chunk c (4 k16 steps)
#pragma unroll
                for (int k = 0; k < 4; k++) {
                    uint32_t ah[2][4], al[2][4];
#pragma unroll
                    for (int mf = 0; mf < 2; mf++) {
                        const uint32_t ad = bufA + (mbase + mf * 16) * ROWB + k * 32 + aoff;
                        ldsm_x4(ah[mf], ad);
                        ldsm_x4(al[mf], ad + TILEB);
                    }
#pragma unroll
                    for (int nl = 0; nl < 4; nl++) {
                        const uint32_t bd = bufA + 2 * TILEB
                                          + (nbase + nl * 16) * ROWB + k * 32 + boff;
                        uint32_t bh[4], bl[4];
                        ldsm_x4(bh, bd);
                        ldsm_x4(bl, bd + TILEB);
#pragma unroll
                        for (int mf = 0; mf < 2; mf++) {
#pragma unroll
                            for (int h2 = 0; h2 < 2; h2++) {
                                float* a = &accs[(mf * 8 + nl * 2 + h2) * 4];
                                mma_16816(a, ah[mf], &bh[2 * h2]);
                                mma_16816(a, ah[mf], &bl[2 * h2]);
                                mma_16816(a, al[mf], &bh[2 * h2]);
                            }
                        }
                    }
                }
                __syncthreads();
                if (c < 2) {
                    // issue chunk c+2 into buffer (c&1)
                    const int kcur = kbase + (c + 2) * 64;
                    const uint32_t base = sb + (c & 1) * BUFB;
#pragma unroll
                    for (int i = 0; i < 4; i++) {
                        const int row = lrow + 32 * i;
                        const uint32_t d = base + row * ROWB + lg * 16;
                        const size_t ea = ((size_t)row * Hh + kcur + lg * 8) * 2;
                        cp16(d,             (const char*)g_hhi + ea);
                        cp16(d + TILEB,     (const char*)g_hlo + ea);
                        const size_t eb = ((size_t)(n0 + row) * Hh + kcur + lg * 8) * 2;
                        cp16(d + 2 * TILEB, (const char*)g_rkT_hi + eb);
                        cp16(d + 3 * TILEB, (const char*)g_rkT_lo + eb);
                    }
                    CP_COMMIT();
                }
            }

            // epilogue: write partials
#pragma unroll
            for (int mf = 0; mf < 2; mf++) {
#pragma unroll
                for (int nf = 0; nf < 8; nf++) {
                    const float* a = &accs[(mf * 8 + nf) * 4];
                    const int row = mbase + mf * 16 + (lane >> 2);
                    const int col = n0 + nbase + (nf >> 1) * 16 + (nf & 1) * 8 + (lane & 3) * 2;
                    float* p = g_rgp + ((size_t)ks * Bb + row) * G3 + col;
                    *(float2*)p = make_float2(a[0], a[1]);
                    *(float2*)(p + (size_t)8 * G3) = make_float2(a[2], a[3]);
                }
            }
            // grid barrier
            __syncthreads();
            if (tid == 0) {
                __threadfence();
                epoch++;
                atomicAdd(&g_bar, 1u);
                while (*(volatile unsigned*)&g_bar < epoch * GRID_GRU) { }
            }
            __syncthreads();
        }

        // ---------------- phase B: gates ----------------
        {
            const float* __restrict__ xgt = g_xg + (size_t)t * Bb * G3;
            const float* __restrict__ hprev = g_hs + (size_t)(t - 1) * Bb * Hh;
            float* __restrict__ hcur = g_hs + (size_t)t * Bb * Hh;
            for (int v = blockIdx.x * 256 + tid; v < (Bb * Hh) / 4; v += GRID_GRU * 256) {
                const int b = v >> 8;
                const int j = (v & 255) << 2;
                const size_t xb = (size_t)b * G3 + j;
                float4 xz = *(const float4*)(xgt + xb);
                float4 xr = *(const float4*)(xgt + xb + Hh);
                float4 xh = *(const float4*)(xgt + xb + 2 * Hh);
                float4 az = make_float4(0.f, 0.f, 0.f, 0.f);
                float4 ar = az, ah = az, hp = az;
                if (t > 0) {
#pragma unroll
                    for (int s = 0; s < 4; s++) {
                        const float* rp = g_rgp + (size_t)s * Bb * G3 + xb;
                        float4 a0 = __ldcg((const float4*)(rp));
                        float4 a1 = __ldcg((const float4*)(rp + Hh));
                        float4 a2 = __ldcg((const float4*)(rp + 2 * Hh));
                        az.x += a0.x; az.y += a0.y; az.z += a0.z; az.w += a0.w;
                        ar.x += a1.x; ar.y += a1.y; ar.z += a1.z; ar.w += a1.w;
                        ah.x += a2.x; ah.y += a2.y; ah.z += a2.z; ah.w += a2.w;
                    }
                    hp = __ldcg((const float4*)(hprev + (size_t)b * Hh + j));
                }
                float4 bz = *(const float4*)(br + j);
                float4 brv = *(const float4*)(br + Hh + j);
                float4 bh = *(const float4*)(br + 2 * Hh + j);
                float4 o;
#define GATE1(C) { \
                float z = sig_(xz.C + az.C + bz.C); \
                float rg = sig_(xr.C + ar.C + brv.C); \
                float th = tanhf(xh.C + rg * (ah.C + bh.C)); \
                o.C = z * hp.C + (1.f - z) * th; }
                GATE1(x) GATE1(y) GATE1(z) GATE1(w)
#undef GATE1
                *(float4*)(hcur + (size_t)b * Hh + j) = o;
                __nv_bfloat16 h0 = __float2bfloat16(o.x);
                __nv_bfloat16 h1 = __float2bfloat16(o.y);
                __nv_bfloat16 h2 = __float2bfloat16(o.z);
                __nv_bfloat16 h3 = __float2bfloat16(o.w);
                union { __nv_bfloat16 bf[4]; uint2 u; } ph, pl;
                ph.bf[0] = h0; ph.bf[1] = h1; ph.bf[2] = h2; ph.bf[3] = h3;
                pl.bf[0] = __float2bfloat16(o.x - __bfloat162float(h0));
                pl.bf[1] = __float2bfloat16(o.y - __bfloat162float(h1));
                pl.bf[2] = __float2bfloat16(o.z - __bfloat162float(h2));
                pl.bf[3] = __float2bfloat16(o.w - __bfloat162float(h3));
                *(uint2*)(g_hhi + (size_t)b * Hh + j) = ph.u;
                *(uint2*)(g_hlo + (size_t)b * Hh + j) = pl.u;
            }
        }
        // grid barrier
        __syncthreads();
        if (tid == 0) {
            __threadfence();
            epoch++;
            atomicAdd(&g_bar, 1u);
            while (*(volatile unsigned*)&g_bar < epoch * GRID_GRU) { }
        }
        __syncthreads();
    }
}

// ---------------------------------------------------------------------------
// Kernel 3: d = relu(hs @ w1 + b1)
// ---------------------------------------------------------------------------
__global__ __launch_bounds__(256) void k_w1relu(
    const float* __restrict__ w1, const float* __restrict__ b1)
{
    __shared__ float As[16][68];
    __shared__ float Bs[16][68];
    const int n0 = blockIdx.x * 64;
    const int m0 = blockIdx.y * 64;
    const int tid = threadIdx.x;
    const int tx = tid & 15, ty = tid >> 4;
    const int a_row = tid >> 2, a_c4 = tid & 3;
    const int b_row = tid >> 4, b_c4 = tid & 15;
    const float* __restrict__ apt = g_hs + (size_t)(m0 + a_row) * Hh;

    float acc[4][4];
#pragma unroll
    for (int i = 0; i < 4; i++)
#pragma unroll
        for (int j = 0; j < 4; j++) acc[i][j] = 0.f;

    for (int k0 = 0; k0 < Hh; k0 += 16) {
        float4 av = *reinterpret_cast<const float4*>(apt + k0 + a_c4 * 4);
        float4 bv = *reinterpret_cast<const float4*>(
            w1 + (size_t)(k0 + b_row) * Dd + n0 + b_c4 * 4);
        As[a_c4 * 4 + 0][a_row] = av.x;
        As[a_c4 * 4 + 1][a_row] = av.y;
        As[a_c4 * 4 + 2][a_row] = av.z;
        As[a_c4 * 4 + 3][a_row] = av.w;
        *reinterpret_cast<float4*>(&Bs[b_row][b_c4 * 4]) = bv;
        __syncthreads();
#pragma unroll
        for (int kk = 0; kk < 16; kk++) {
            float4 a = *reinterpret_cast<const float4*>(&As[kk][ty * 4]);
            float4 b = *reinterpret_cast<const float4*>(&Bs[kk][tx * 4]);
            float aa[4] = {a.x, a.y, a.z, a.w};
            float bb[4] = {b.x, b.y, b.z, b.w};
#pragma unroll
            for (int i = 0; i < 4; i++)
#pragma unroll
                for (int j = 0; j < 4; j++)
                    acc[i][j] = fmaf(aa[i], bb[j], acc[i][j]);
        }
        __syncthreads();
    }
#pragma unroll
    for (int i = 0; i < 4; i++) {
        int row = m0 + ty * 4 + i;
        int col = n0 + tx * 4;
        float4 o;
        o.x = fmaxf(acc[i][0] + b1[col + 0], 0.f);
        o.y = fmaxf(acc[i][1] + b1[col + 1], 0.f);
        o.z = fmaxf(acc[i][2] + b1[col + 2], 0.f);
        o.w = fmaxf(acc[i][3] + b1[col + 3], 0.f);
        *reinterpret_cast<float4*>(&g_d[(size_t)row * Dd + col]) = o;
    }
}

// ---------------------------------------------------------------------------
// Kernel 4: logits = d @ w2 + b2 -> d_out as [B][T][V]
// ---------------------------------------------------------------------------
__global__ __launch_bounds__(256) void k_w2(
    const float* __restrict__ w2, const float* __restrict__ b2,
    float* __restrict__ out)
{
    __shared__ float As[16][68];
    __shared__ float Bs[16][68];
    const int n0 = blockIdx.x * 64;
    const int m0 = blockIdx.y * 64;
    const int tid = threadIdx.x;
    const int tx = tid & 15, ty = tid >> 4;
    const int a_row = tid >> 2, a_c4 = tid & 3;
    const int b_row = tid >> 4, b_c4 = tid & 15;
    const float* __restrict__ apt = g_d + (size_t)(m0 + a_row) * Dd;
    const bool full = (n0 + 64 <= Vv);

    float acc[4][4];
#pragma unroll
    for (int i = 0; i < 4; i++)
#pragma unroll
        for (int j = 0; j < 4; j++) acc[i][j] = 0.f;

    for (int k0 = 0; k0 < Dd; k0 += 16) {
        float4 av = *reinterpret_cast<const float4*>(apt + k0 + a_c4 * 4);
        As[a_c4 * 4 + 0][a_row] = av.x;
        As[a_c4 * 4 + 1][a_row] = av.y;
        As[a_c4 * 4 + 2][a_row] = av.z;
        As[a_c4 * 4 + 3][a_row] = av.w;
        if (full) {
            float4 bv = *reinterpret_cast<const float4*>(
                w2 + (size_t)(k0 + b_row) * Vv + n0 + b_c4 * 4);
            *reinterpret_cast<float4*>(&Bs[b_row][b_c4 * 4]) = bv;
        } else {
#pragma unroll
            for (int c = 0; c < 4; c++) {
                int col = n0 + b_c4 * 4 + c;
                Bs[b_row][b_c4 * 4 + c] =
                    (col < Vv) ? w2[(size_t)(k0 + b_row) * Vv + col] : 0.f;
            }
        }
        __syncthreads();
#pragma unroll
        for (int kk = 0; kk < 16; kk++) {
            float4 a = *reinterpret_cast<const float4*>(&As[kk][ty * 4]);
            float4 b = *reinterpret_cast<const float4*>(&Bs[kk][tx * 4]);
            float aa[4] = {a.x, a.y, a.z, a.w};
            float bb[4] = {b.x, b.y, b.z, b.w};
#pragma unroll
            for (int i = 0; i < 4; i++)
#pragma unroll
                for (int j = 0; j < 4; j++)
                    acc[i][j] = fmaf(aa[i], bb[j], acc[i][j]);
        }
        __syncthreads();
    }
#pragma unroll
    for (int i = 0; i < 4; i++) {
        int rr = m0 + ty * 4 + i;
        int t = rr >> 7, b = rr & 127;
        size_t obase = ((size_t)b * Tt + t) * Vv;
#pragma unroll
        for (int j = 0; j < 4; j++) {
            int col = n0 + tx * 4 + j;
            if (col < Vv) out[obase + col] = acc[i][j] + b2[col];
        }
    }
}

// ---------------------------------------------------------------------------
// Kernel 5: softmax rows of 10000 with logits*50
// ---------------------------------------------------------------------------
__global__ __launch_bounds__(256) void k_softmax(float* __restrict__ out)
{
    float* __restrict__ p = out + (size_t)blockIdx.x * Vv;
    const int tid = threadIdx.x;
    float vals[40];
    float mx = -1e30f;
#pragma unroll
    for (int i = 0; i < 40; i++) {
        int idx = tid + (i << 8);
        if (idx < Vv) {
            float v = p[idx] * 50.0f;
            vals[i] = v;
            mx = fmaxf(mx, v);
        } else {
            vals[i] = -1e30f;
        }
    }
    __shared__ float redm[8];
    __shared__ float reds[8];
#pragma unroll
    for (int o = 16; o; o >>= 1) mx = fmaxf(mx, __shfl_xor_sync(0xffffffffu, mx, o));
    if ((tid & 31) == 0) redm[tid >> 5] = mx;
    __syncthreads();
    mx = redm[0];
#pragma unroll
    for (int w = 1; w < 8; w++) mx = fmaxf(mx, redm[w]);

    float s = 0.f;
#pragma unroll
    for (int i = 0; i < 40; i++) {
        int idx = tid + (i << 8);
        if (idx < Vv) {
            float e = expf(vals[i] - mx);
            vals[i] = e;
            s += e;
        }
    }
#pragma unroll
    for (int o = 16; o; o >>= 1) s += __shfl_xor_sync(0xffffffffu, s, o);
    if ((tid & 31) == 0) reds[tid >> 5] = s;
    __syncthreads();
    float tot = 0.f;
#pragma unroll
    for (int w = 0; w < 8; w++) tot += reds[w];
    float inv = 1.0f / tot;
#pragma unroll
    for (int i = 0; i < 40; i++) {
        int idx = tid + (i << 8);
        if (idx < Vv) p[idx] = vals[i] * inv;
    }
}

// ---------------------------------------------------------------------------
extern "C" void kernel_launch(void* const* d_in, const int* in_sizes, int n_in,
                              void* d_out, int out_size)
{
    const int*   tokens = (const int*)  d_in[0];
    const float* emb    = (const float*)d_in[1];
    const float* gk     = (const float*)d_in[2];
    const float* grk    = (const float*)d_in[3];
    const float* gbi    = (const float*)d_in[4];
    const float* gbr    = (const float*)d_in[5];
    const float* w1     = (const float*)d_in[6];
    const float* b1     = (const float*)d_in[7];
    const float* w2     = (const float*)d_in[8];
    const float* b2     = (const float*)d_in[9];
    float* out = (float*)d_out;

    cudaFuncSetAttribute(k_gru_mma, cudaFuncAttributeMaxDynamicSharedMemorySize, GRU_SMEM);

    dim3 blk(256);
    k_reset<<<1, 1>>>();
    k_rk_split<<<dim3(G3 / 32, Hh / 32), blk>>>(grk);
    k_embed_gemm<<<dim3(G3 / 64, MROWS / 64), blk>>>(tokens, emb, gk, gbi);
    k_gru_mma<<<GRID_GRU, blk, GRU_SMEM>>>(gbr);
    k_w1relu<<<dim3(Dd / 64, MROWS / 64), blk>>>(w1, b1);
    k_w2<<<dim3((Vv + 63) / 64, MROWS / 64), blk>>>(w2, b2, out);
    k_softmax<<<MROWS, blk>>>(out);
}